// round 12
// baseline (speedup 1.0000x reference)
#include <cuda_runtime.h>
#include <cuda_fp16.h>
#include <stdint.h>
#include <string.h>

// FieldAwareFM: B=16384, F=10, D=8.
// out[b] = b_lin + sum_f w[idx_f] + sum_{f<g} <emb[f][idx_g], emb[g][idx_f]>
//
// R1-R9 localization: runtime bound by 32B-SECTOR request count (invariant to
// mechanism, cache state, line density, instruction/wavefront/shuffle counts).
// This round reduces sectors: loads whose COLUMN (index-source) field is 5..9
// (45 of 90 per sample) read from an fp16 transposed block
//   g_concat[j][f][0..7] = half(emb[f][185000+j][0..7])
// so one column's 9 rows = 144B contiguous (~5 sectors instead of 9).
// Expected sectors/sample: ~101 -> ~72.
//
// Layout (R7): slot = 32t+lane, pair p = slot>>1, h = slot&1. Lane loads the
// 16B (fp32) / 8B (fp16) half h of both rows of its pair, accumulates the
// partial dot locally; halves combine in the final warp reduction.

#define BATCH       16384
#define NUM_FIELDS  10
#define INPUT_DIM   188610
#define NUM_PAIRS   45
#define NUM_ROUNDS  3
#define CONCAT_ROWS 3610
#define CONCAT_G0   185000

__device__ __align__(16) __half g_concat[CONCAT_ROWS * 80];   // [j][f][8], 578KB

__constant__ int c_offsets[NUM_FIELDS] = {
    0, 100000, 150000, 170000, 180000, 185000, 187000, 188000, 188500, 188600
};

// pair p -> (f, g), f < g   (pad p=45..47 -> (0,1), masked in accumulate)
__constant__ signed char c_pf[48] = {
    0,0,0,0,0,0,0,0,0, 1,1,1,1,1,1,1,1, 2,2,2,2,2,2,2, 3,3,3,3,3,3,
    4,4,4,4,4, 5,5,5,5, 6,6,6, 7,7, 8, 0,0,0
};
__constant__ signed char c_pg[48] = {
    1,2,3,4,5,6,7,8,9, 2,3,4,5,6,7,8,9, 3,4,5,6,7,8,9, 4,5,6,7,8,9,
    5,6,7,8,9, 6,7,8,9, 7,8,9, 8,9, 9, 1,1,1
};

__device__ __forceinline__ uint32_t h2_bits(__half2 h) {
    uint32_t u;
    memcpy(&u, &h, 4);
    return u;
}

// ---- pre-kernel: fp32 -> fp16 transposed hot block (1.16MB read, 0.58MB write) ----
__global__ __launch_bounds__(256)
void build_concat(const float* __restrict__ emb)
{
    const int u = blockIdx.x * 256 + threadIdx.x;       // (f, j)
    if (u >= NUM_FIELDS * CONCAT_ROWS) return;
    const int f = u / CONCAT_ROWS;
    const int j = u - f * CONCAT_ROWS;
    const float4 a = *(const float4*)(emb + ((size_t)f * INPUT_DIM + CONCAT_G0 + j) * 8);
    const float4 b = *(const float4*)(emb + ((size_t)f * INPUT_DIM + CONCAT_G0 + j) * 8 + 4);
    uint4 packed;
    packed.x = h2_bits(__floats2half2_rn(a.x, a.y));
    packed.y = h2_bits(__floats2half2_rn(a.z, a.w));
    packed.z = h2_bits(__floats2half2_rn(b.x, b.y));
    packed.w = h2_bits(__floats2half2_rn(b.z, b.w));
    *(uint4*)(g_concat + (size_t)j * 80 + f * 8) = packed;
}

__device__ __forceinline__ float4 load_half4(const void* addr)
{
    // 8B load: 4 halves -> 4 floats
    uint2 r = __ldg((const uint2*)addr);
    __half2 h01, h23;
    memcpy(&h01, &r.x, 4);
    memcpy(&h23, &r.y, 4);
    float2 f01 = __half22float2(h01);
    float2 f23 = __half22float2(h23);
    return make_float4(f01.x, f01.y, f23.x, f23.y);
}

__global__ __launch_bounds__(256)
void ffm_kernel(const int* __restrict__ x,
                const float* __restrict__ w,
                const float* __restrict__ b_lin,
                const float* __restrict__ emb,
                float* __restrict__ out)
{
    const int warp_in_block = threadIdx.x >> 5;
    const int lane          = threadIdx.x & 31;
    const int b             = blockIdx.x * (blockDim.x >> 5) + warp_in_block;
    const unsigned full     = 0xffffffffu;

    const float bias = __ldg(&b_lin[0]);

    // lanes 0..9: this sample's global indices (coalesced 40B)
    int my_gid = 0;
    if (lane < NUM_FIELDS) {
        my_gid = x[b * NUM_FIELDS + lane] + c_offsets[lane];
    }
    float lin = 0.0f;
    if (lane < NUM_FIELDS) {
        lin = __ldg(&w[my_gid]);
    }

    const int h = lane & 1;   // half of the row

    // ---- Phase A: decode pairs, compute addresses/flags ----
    const void* pa[NUM_ROUNDS];
    const void* pb[NUM_ROUNDS];
    bool fa16[NUM_ROUNDS], fb16[NUM_ROUNDS], valid[NUM_ROUNDS];
#pragma unroll
    for (int t = 0; t < NUM_ROUNDS; t++) {
        const int p = ((t << 5) + lane) >> 1;
        const int f = (int)c_pf[p];
        const int g = (int)c_pg[p];
        const int gid_g = __shfl_sync(full, my_gid, g);
        const int gid_f = __shfl_sync(full, my_gid, f);
        valid[t] = (p < NUM_PAIRS);
        // side A: emb[f][idx_g] (column g); fp16 concat when g>=5
        fa16[t] = (g >= 5);
        pa[t] = fa16[t]
            ? (const void*)(g_concat + (size_t)(gid_g - CONCAT_G0) * 80 + f * 8 + h * 4)
            : (const void*)(emb + ((size_t)f * INPUT_DIM + (size_t)gid_g) * 8 + h * 4);
        // side B: emb[g][idx_f] (column f); fp16 concat when f>=5
        fb16[t] = (f >= 5);
        pb[t] = fb16[t]
            ? (const void*)(g_concat + (size_t)(gid_f - CONCAT_G0) * 80 + g * 8 + h * 4)
            : (const void*)(emb + ((size_t)g * INPUT_DIM + (size_t)gid_f) * 8 + h * 4);
    }

    // ---- issue all loads (batched, independent) ----
    float4 va[NUM_ROUNDS], vb[NUM_ROUNDS];
#pragma unroll
    for (int t = 0; t < NUM_ROUNDS; t++) {
        va[t] = fa16[t] ? load_half4(pa[t]) : __ldg((const float4*)pa[t]);
        vb[t] = fb16[t] ? load_half4(pb[t]) : __ldg((const float4*)pb[t]);
    }

    // ---- Phase B: local partial dots ----
    float ffm = 0.0f;
#pragma unroll
    for (int t = 0; t < NUM_ROUNDS; t++) {
        float d = va[t].x * vb[t].x + va[t].y * vb[t].y
                + va[t].z * vb[t].z + va[t].w * vb[t].w;
        if (valid[t]) ffm += d;
    }

    float acc = ffm + lin;

#pragma unroll
    for (int off = 16; off > 0; off >>= 1) {
        acc += __shfl_xor_sync(full, acc, off);
    }

    if (lane == 0) {
        out[b] = acc + bias;
    }
}

extern "C" void kernel_launch(void* const* d_in, const int* in_sizes, int n_in,
                              void* d_out, int out_size)
{
    (void)in_sizes; (void)n_in; (void)out_size;
    const int*   x     = (const int*)d_in[0];
    const float* w     = (const float*)d_in[1];
    const float* b_lin = (const float*)d_in[2];
    const float* emb   = (const float*)d_in[3];
    float*       out   = (float*)d_out;

    // 1) build fp16 transposed hot block (fields 5..9), deterministic each launch
    const int units = NUM_FIELDS * CONCAT_ROWS;              // 36100
    build_concat<<<(units + 255) / 256, 256>>>(emb);

    // 2) main kernel
    const int warps_per_block = 8;                // 256 threads
    const int blocks = BATCH / warps_per_block;   // 2048
    ffm_kernel<<<blocks, warps_per_block * 32>>>(x, w, b_lin, emb, out);
}